// round 1
// baseline (speedup 1.0000x reference)
#include <cuda_runtime.h>
#include <cstdint>

// Problem constants
#define BB   256
#define NN   512
#define DD   128
#define C1   256          // 2*D
#define C2   128
#define BN_  131072L      // BB*NN

// Scratch (device globals; no cudaMalloc allowed)
__device__ float g_xcat[BN_ * C1];   // concat(aggr_feat, aggr_instance), (bn, c)
__device__ float g_h1[BN_ * C1];     // raw conv1 output, (bn, o)
__device__ float g_h2[BN_ * C2];     // raw conv2 output, (bn, o)
__device__ float g_stats[768];       // [0,256) sum1, [256,512) sq1, [512,640) sum2, [640,768) sq2
__device__ float g_aff[768];         // [0,256) scale1, [256,512) shift1, [512,640) scale2, [640,768) shift2

using u64 = unsigned long long;

__device__ __forceinline__ u64 pack2(float x, float y) {
    u64 u; asm("mov.b64 %0, {%1, %2};" : "=l"(u) : "f"(x), "f"(y)); return u;
}
__device__ __forceinline__ void unpack2(u64 u, float& x, float& y) {
    asm("mov.b64 {%0, %1}, %2;" : "=f"(x), "=f"(y) : "l"(u));
}
__device__ __forceinline__ u64 fma2(u64 a, u64 b, u64 c) {
    u64 d; asm("fma.rn.f32x2 %0, %1, %2, %3;" : "=l"(d) : "l"(a), "l"(b), "l"(c)); return d;
}
__device__ __forceinline__ u64 add2(u64 a, u64 b) {
    u64 d; asm("add.rn.f32x2 %0, %1, %2;" : "=l"(d) : "l"(a), "l"(b)); return d;
}
__device__ __forceinline__ float lrelu(float v) { return v >= 0.f ? v : 0.01f * v; }

// ---------------------------------------------------------------------------
// K0: zero stats accumulators
// ---------------------------------------------------------------------------
__global__ void k_zero() {
    int t = threadIdx.x;
    if (t < 768) g_stats[t] = 0.f;
}

// ---------------------------------------------------------------------------
// K1: fused  aggr = (E .* (1-I)) @ P / rowsum  for both edge tensors.
// Block: 64 rows (i) of one batch, all 128 d-cols for both edges -> 64x256 tile.
// Threads 256: r = tid/32 (8 row groups of 8 rows), c = tid%32
//   c in [0,16): edge_d cols (c)*8..   ;  c in [16,32): edge_i cols (c-16)*8..
// ---------------------------------------------------------------------------
__global__ __launch_bounds__(256) void k_aggr(const float* __restrict__ Ed,
                                              const float* __restrict__ Ei,
                                              const float* __restrict__ P) {
    __shared__ __align__(16) float sEd[32][64];   // [k][i]
    __shared__ __align__(16) float sEi[32][64];
    __shared__ __align__(16) float sP[32][128];   // [k][d]
    __shared__ float srs[2][64];

    const int b  = blockIdx.y;
    const int i0 = blockIdx.x * 64;
    const int tid = threadIdx.x;
    const int c = tid & 31, r = tid >> 5;

    const float* EdB = Ed + ((long)b * NN + i0) * NN;
    const float* EiB = Ei + ((long)b * NN + i0) * NN;
    const float* PB  = P  + (long)b * NN * DD;

    u64 acc[4][8];
    #pragma unroll
    for (int x = 0; x < 4; x++)
        #pragma unroll
        for (int y = 0; y < 8; y++) acc[x][y] = 0ULL;
    u64 rsum[4] = {0ULL, 0ULL, 0ULL, 0ULL};

    const bool isD = (c < 16);
    const int  cc8 = (c & 15) << 3;

    for (int k0 = 0; k0 < NN; k0 += 32) {
        // load E tiles (64 rows x 32 k), transpose to [k][i], zero diagonal
        #pragma unroll
        for (int t = 0; t < 2; t++) {
            int idx = tid + t * 256;            // float4 units, 0..511
            int row = idx >> 3;
            int col = (idx & 7) << 2;
            int gi = i0 + row, gj = k0 + col;
            float4 v = *(const float4*)(EdB + (long)row * NN + k0 + col);
            float4 w = *(const float4*)(EiB + (long)row * NN + k0 + col);
            if (gj + 0 == gi) { v.x = 0.f; w.x = 0.f; }
            if (gj + 1 == gi) { v.y = 0.f; w.y = 0.f; }
            if (gj + 2 == gi) { v.z = 0.f; w.z = 0.f; }
            if (gj + 3 == gi) { v.w = 0.f; w.w = 0.f; }
            sEd[col + 0][row] = v.x; sEd[col + 1][row] = v.y;
            sEd[col + 2][row] = v.z; sEd[col + 3][row] = v.w;
            sEi[col + 0][row] = w.x; sEi[col + 1][row] = w.y;
            sEi[col + 2][row] = w.z; sEi[col + 3][row] = w.w;
        }
        // load P tile (32 k x 128 d)
        #pragma unroll
        for (int t = 0; t < 4; t++) {
            int idx = tid + t * 256;            // 0..1023
            int row = idx >> 5;
            int col = (idx & 31) << 2;
            *(float4*)&sP[row][col] = *(const float4*)(PB + (long)(k0 + row) * DD + col);
        }
        __syncthreads();

        #pragma unroll
        for (int jj = 0; jj < 32; jj++) {
            const float* ap = isD ? &sEd[jj][r * 8] : &sEi[jj][r * 8];
            ulonglong2 av0 = *(const ulonglong2*)ap;
            ulonglong2 av1 = *(const ulonglong2*)(ap + 4);
            u64 a2[4] = {av0.x, av0.y, av1.x, av1.y};
            float bf[8];
            *(float4*)bf       = *(const float4*)&sP[jj][cc8];
            *(float4*)(bf + 4) = *(const float4*)&sP[jj][cc8 + 4];
            u64 bd[8];
            #pragma unroll
            for (int y = 0; y < 8; y++) bd[y] = pack2(bf[y], bf[y]);
            #pragma unroll
            for (int x = 0; x < 4; x++)
                #pragma unroll
                for (int y = 0; y < 8; y++)
                    acc[x][y] = fma2(a2[x], bd[y], acc[x][y]);
            if (c == 0 || c == 16) {
                #pragma unroll
                for (int x = 0; x < 4; x++) rsum[x] = add2(rsum[x], a2[x]);
            }
        }
        __syncthreads();
    }

    // rowsums -> smem (edges are non-negative, so sum == sum of |.|)
    if (c == 0 || c == 16) {
        int h = (c == 16);
        #pragma unroll
        for (int x = 0; x < 4; x++) {
            float lo, hi; unpack2(rsum[x], lo, hi);
            srs[h][r * 8 + 2 * x]     = lo;
            srs[h][r * 8 + 2 * x + 1] = hi;
        }
    }
    __syncthreads();

    const int h = isD ? 0 : 1;
    const int colbase = cc8 + h * 128;
    #pragma unroll
    for (int x = 0; x < 4; x++) {
        float lo[8], hi[8];
        #pragma unroll
        for (int y = 0; y < 8; y++) unpack2(acc[x][y], lo[y], hi[y]);
        #pragma unroll
        for (int s = 0; s < 2; s++) {
            int lrow = r * 8 + 2 * x + s;
            int gi = i0 + lrow;
            float inv = 1.f / fmaxf(srs[h][lrow], 1e-12f);
            float* sel = s ? hi : lo;
            float4* dst = (float4*)&g_xcat[((long)b * NN + gi) * C1 + colbase];
            dst[0] = make_float4(sel[0] * inv, sel[1] * inv, sel[2] * inv, sel[3] * inv);
            dst[1] = make_float4(sel[4] * inv, sel[5] * inv, sel[6] * inv, sel[7] * inv);
        }
    }
}

// ---------------------------------------------------------------------------
// K2: h1[m,o] = sum_c xcat[m,c] * W1[o,c]  (m = 64 rows/block, o = 256)
//     + per-channel sum / sumsq partials via smem + global atomics
// ---------------------------------------------------------------------------
__global__ __launch_bounds__(256) void k_gemm1(const float* __restrict__ W1) {
    __shared__ __align__(16) float sA[32][64];    // [k][m]
    __shared__ __align__(16) float sW[32][256];   // [k][o]
    __shared__ float ssum[256];
    __shared__ float ssq[256];

    const long m0 = (long)blockIdx.x * 64;
    const int tid = threadIdx.x;
    const int c = tid & 31, r = tid >> 5;

    u64 acc[4][8];
    #pragma unroll
    for (int x = 0; x < 4; x++)
        #pragma unroll
        for (int y = 0; y < 8; y++) acc[x][y] = 0ULL;

    ssum[tid] = 0.f; ssq[tid] = 0.f;

    for (int k0 = 0; k0 < C1; k0 += 32) {
        #pragma unroll
        for (int t = 0; t < 2; t++) {
            int idx = tid + t * 256;            // 0..511
            int row = idx >> 3;
            int col = (idx & 7) << 2;
            float4 v = *(const float4*)&g_xcat[(m0 + row) * C1 + k0 + col];
            sA[col + 0][row] = v.x; sA[col + 1][row] = v.y;
            sA[col + 2][row] = v.z; sA[col + 3][row] = v.w;
        }
        #pragma unroll
        for (int t = 0; t < 8; t++) {
            int idx = tid + t * 256;            // 0..2047
            int o = idx >> 3;
            int col = (idx & 7) << 2;
            float4 v = *(const float4*)&W1[o * C1 + k0 + col];
            sW[col + 0][o] = v.x; sW[col + 1][o] = v.y;
            sW[col + 2][o] = v.z; sW[col + 3][o] = v.w;
        }
        __syncthreads();
        #pragma unroll
        for (int jj = 0; jj < 32; jj++) {
            const float* ap = &sA[jj][r * 8];
            ulonglong2 av0 = *(const ulonglong2*)ap;
            ulonglong2 av1 = *(const ulonglong2*)(ap + 4);
            u64 a2[4] = {av0.x, av0.y, av1.x, av1.y};
            float bf[8];
            *(float4*)bf       = *(const float4*)&sW[jj][c * 8];
            *(float4*)(bf + 4) = *(const float4*)&sW[jj][c * 8 + 4];
            u64 bd[8];
            #pragma unroll
            for (int y = 0; y < 8; y++) bd[y] = pack2(bf[y], bf[y]);
            #pragma unroll
            for (int x = 0; x < 4; x++)
                #pragma unroll
                for (int y = 0; y < 8; y++)
                    acc[x][y] = fma2(a2[x], bd[y], acc[x][y]);
        }
        __syncthreads();
    }

    float psum[8], psq[8];
    #pragma unroll
    for (int y = 0; y < 8; y++) { psum[y] = 0.f; psq[y] = 0.f; }

    #pragma unroll
    for (int x = 0; x < 4; x++) {
        float lo[8], hi[8];
        #pragma unroll
        for (int y = 0; y < 8; y++) {
            unpack2(acc[x][y], lo[y], hi[y]);
            psum[y] += lo[y] + hi[y];
            psq[y]  += lo[y] * lo[y] + hi[y] * hi[y];
        }
        #pragma unroll
        for (int s = 0; s < 2; s++) {
            int lrow = r * 8 + 2 * x + s;
            float* sel = s ? hi : lo;
            float4* dst = (float4*)&g_h1[(m0 + lrow) * C1 + c * 8];
            dst[0] = make_float4(sel[0], sel[1], sel[2], sel[3]);
            dst[1] = make_float4(sel[4], sel[5], sel[6], sel[7]);
        }
    }
    #pragma unroll
    for (int y = 0; y < 8; y++) {
        atomicAdd(&ssum[c * 8 + y], psum[y]);
        atomicAdd(&ssq[c * 8 + y], psq[y]);
    }
    __syncthreads();
    atomicAdd(&g_stats[tid], ssum[tid]);
    atomicAdd(&g_stats[256 + tid], ssq[tid]);
}

// ---------------------------------------------------------------------------
// K3/K5: stats -> (scale, shift)
// ---------------------------------------------------------------------------
__global__ void k_bnaff(const float* __restrict__ g, const float* __restrict__ b,
                        int C, int statoff, int affoff) {
    int o = threadIdx.x;
    if (o < C) {
        const float inv_cnt = 1.f / 131072.f;
        float mean = g_stats[statoff + o] * inv_cnt;
        float var  = g_stats[statoff + C + o] * inv_cnt - mean * mean;
        float sc = g[o] * rsqrtf(var + 1e-5f);
        g_aff[affoff + o]     = sc;
        g_aff[affoff + C + o] = b[o] - mean * sc;
    }
}

// ---------------------------------------------------------------------------
// K4: h2[m,o] = sum_c lrelu(scale1[c]*h1[m,c]+shift1[c]) * W2[o,c]
//     + stats for BN2.  64 rows/block, 128 cols; micro 8x4 per thread.
// ---------------------------------------------------------------------------
__global__ __launch_bounds__(256) void k_gemm2(const float* __restrict__ W2) {
    __shared__ __align__(16) float sA[32][64];
    __shared__ __align__(16) float sW[32][128];
    __shared__ float saff[2][256];
    __shared__ float ssum[128];
    __shared__ float ssq[128];

    const long m0 = (long)blockIdx.x * 64;
    const int tid = threadIdx.x;
    const int c = tid & 31, r = tid >> 5;

    saff[0][tid] = g_aff[tid];         // scale1
    saff[1][tid] = g_aff[256 + tid];   // shift1
    if (tid < 128) { ssum[tid] = 0.f; ssq[tid] = 0.f; }

    u64 acc[4][4];
    #pragma unroll
    for (int x = 0; x < 4; x++)
        #pragma unroll
        for (int y = 0; y < 4; y++) acc[x][y] = 0ULL;

    __syncthreads();

    for (int k0 = 0; k0 < C1; k0 += 32) {
        #pragma unroll
        for (int t = 0; t < 2; t++) {
            int idx = tid + t * 256;
            int row = idx >> 3;
            int col = (idx & 7) << 2;
            float4 v = *(const float4*)&g_h1[(m0 + row) * C1 + k0 + col];
            int ch = k0 + col;
            v.x = lrelu(saff[0][ch + 0] * v.x + saff[1][ch + 0]);
            v.y = lrelu(saff[0][ch + 1] * v.y + saff[1][ch + 1]);
            v.z = lrelu(saff[0][ch + 2] * v.z + saff[1][ch + 2]);
            v.w = lrelu(saff[0][ch + 3] * v.w + saff[1][ch + 3]);
            sA[col + 0][row] = v.x; sA[col + 1][row] = v.y;
            sA[col + 2][row] = v.z; sA[col + 3][row] = v.w;
        }
        #pragma unroll
        for (int t = 0; t < 4; t++) {
            int idx = tid + t * 256;            // 0..1023
            int o = idx >> 3;
            int col = (idx & 7) << 2;
            float4 v = *(const float4*)&W2[o * C1 + k0 + col];
            sW[col + 0][o] = v.x; sW[col + 1][o] = v.y;
            sW[col + 2][o] = v.z; sW[col + 3][o] = v.w;
        }
        __syncthreads();
        #pragma unroll
        for (int jj = 0; jj < 32; jj++) {
            const float* ap = &sA[jj][r * 8];
            ulonglong2 av0 = *(const ulonglong2*)ap;
            ulonglong2 av1 = *(const ulonglong2*)(ap + 4);
            u64 a2[4] = {av0.x, av0.y, av1.x, av1.y};
            float bf[4];
            *(float4*)bf = *(const float4*)&sW[jj][c * 4];
            u64 bd[4];
            #pragma unroll
            for (int y = 0; y < 4; y++) bd[y] = pack2(bf[y], bf[y]);
            #pragma unroll
            for (int x = 0; x < 4; x++)
                #pragma unroll
                for (int y = 0; y < 4; y++)
                    acc[x][y] = fma2(a2[x], bd[y], acc[x][y]);
        }
        __syncthreads();
    }

    float psum[4], psq[4];
    #pragma unroll
    for (int y = 0; y < 4; y++) { psum[y] = 0.f; psq[y] = 0.f; }

    #pragma unroll
    for (int x = 0; x < 4; x++) {
        float lo[4], hi[4];
        #pragma unroll
        for (int y = 0; y < 4; y++) {
            unpack2(acc[x][y], lo[y], hi[y]);
            psum[y] += lo[y] + hi[y];
            psq[y]  += lo[y] * lo[y] + hi[y] * hi[y];
        }
        #pragma unroll
        for (int s = 0; s < 2; s++) {
            int lrow = r * 8 + 2 * x + s;
            float* sel = s ? hi : lo;
            *(float4*)&g_h2[(m0 + lrow) * C2 + c * 4] =
                make_float4(sel[0], sel[1], sel[2], sel[3]);
        }
    }
    #pragma unroll
    for (int y = 0; y < 4; y++) {
        atomicAdd(&ssum[c * 4 + y], psum[y]);
        atomicAdd(&ssq[c * 4 + y], psq[y]);
    }
    __syncthreads();
    if (tid < 128) {
        atomicAdd(&g_stats[512 + tid], ssum[tid]);
        atomicAdd(&g_stats[640 + tid], ssq[tid]);
    }
}

// ---------------------------------------------------------------------------
// K6: out = lrelu(scale2*h2 + shift2)
// ---------------------------------------------------------------------------
__global__ __launch_bounds__(256) void k_final(float* __restrict__ out) {
    long idx = ((long)blockIdx.x * blockDim.x + threadIdx.x);   // float4 index
    long e = idx * 4;
    int ch = (int)(e & 127);
    float4 v = *(const float4*)&g_h2[e];
    v.x = lrelu(g_aff[512 + ch + 0] * v.x + g_aff[640 + ch + 0]);
    v.y = lrelu(g_aff[512 + ch + 1] * v.y + g_aff[640 + ch + 1]);
    v.z = lrelu(g_aff[512 + ch + 2] * v.z + g_aff[640 + ch + 2]);
    v.w = lrelu(g_aff[512 + ch + 3] * v.w + g_aff[640 + ch + 3]);
    *(float4*)&out[e] = v;
}

// ---------------------------------------------------------------------------
extern "C" void kernel_launch(void* const* d_in, const int* in_sizes, int n_in,
                              void* d_out, int out_size) {
    const float* Ed = (const float*)d_in[0];
    const float* Ei = (const float*)d_in[1];
    const float* P  = (const float*)d_in[2];
    const float* W1 = (const float*)d_in[3];
    const float* g1 = (const float*)d_in[4];
    const float* b1 = (const float*)d_in[5];
    const float* W2 = (const float*)d_in[6];
    const float* g2 = (const float*)d_in[7];
    const float* b2 = (const float*)d_in[8];
    float* out = (float*)d_out;

    k_zero<<<1, 768>>>();
    dim3 ga(NN / 64, BB);
    k_aggr<<<ga, 256>>>(Ed, Ei, P);
    k_gemm1<<<(int)(BN_ / 64), 256>>>(W1);
    k_bnaff<<<1, 256>>>(g1, b1, 256, 0, 0);
    k_gemm2<<<(int)(BN_ / 64), 256>>>(W2);
    k_bnaff<<<1, 128>>>(g2, b2, 128, 512, 512);
    k_final<<<(int)(BN_ * C2 / 4 / 256), 256>>>(out);
}

// round 6
// speedup vs baseline: 1.5218x; 1.5218x over previous
#include <cuda_runtime.h>
#include <cuda_bf16.h>
#include <cstdint>

// Problem constants
#define BB   256
#define NN   512
#define DD   128
#define C1   256          // 2*D
#define C2   128
#define BN_  131072L      // BB*NN

// Scratch (device globals; no cudaMalloc allowed)
__device__ float g_xcat[BN_ * C1];
__device__ float g_h1[BN_ * C1];
__device__ float g_h2[BN_ * C2];
__device__ float g_stats[768];
__device__ float g_aff[768];
__device__ __nv_bfloat16 g_pt_hi[(long)BB * DD * NN];   // P^T hi, [b][d][j]
__device__ __nv_bfloat16 g_pt_lo[(long)BB * DD * NN];   // P^T lo

using u64 = unsigned long long;

__device__ __forceinline__ u64 pack2(float x, float y) {
    u64 u; asm("mov.b64 %0, {%1, %2};" : "=l"(u) : "f"(x), "f"(y)); return u;
}
__device__ __forceinline__ void unpack2(u64 u, float& x, float& y) {
    asm("mov.b64 {%0, %1}, %2;" : "=f"(x), "=f"(y) : "l"(u));
}
__device__ __forceinline__ u64 fma2(u64 a, u64 b, u64 c) {
    u64 d; asm("fma.rn.f32x2 %0, %1, %2, %3;" : "=l"(d) : "l"(a), "l"(b), "l"(c)); return d;
}
__device__ __forceinline__ float lrelu(float v) { return v >= 0.f ? v : 0.01f * v; }

__device__ __forceinline__ uint32_t smem_u32(const void* p) {
    uint32_t a;
    asm("{ .reg .u64 t; cvta.to.shared.u64 t, %1; cvt.u32.u64 %0, t; }" : "=r"(a) : "l"(p));
    return a;
}

// hi = exact-truncation bf16 pair packed via PRMT
__device__ __forceinline__ uint32_t prmt_hi(uint32_t a, uint32_t b) {
    uint32_t r; asm("prmt.b32 %0, %1, %2, 0x7632;" : "=r"(r) : "r"(a), "r"(b)); return r;
}
// packed cvt: low half <- x, high half <- y
__device__ __forceinline__ uint32_t cvt_bf16x2(float x, float y) {
    uint32_t r; asm("cvt.rn.bf16x2.f32 %0, %1, %2;" : "=r"(r) : "f"(y), "f"(x)); return r;
}
__device__ __forceinline__ float trunc_bf(float x) {
    return __uint_as_float(__float_as_uint(x) & 0xFFFF0000u);
}

#define LDMX4(r, addr) \
    asm volatile("ldmatrix.sync.aligned.m8n8.x4.shared.b16 {%0,%1,%2,%3}, [%4];" \
        : "=r"((r)[0]), "=r"((r)[1]), "=r"((r)[2]), "=r"((r)[3]) : "r"(addr))

#define MMA_BF16(d, a, b0v, b1v) \
    asm volatile("mma.sync.aligned.m16n8k16.row.col.f32.bf16.bf16.f32 " \
        "{%0,%1,%2,%3}, {%4,%5,%6,%7}, {%8,%9}, {%0,%1,%2,%3};" \
        : "+f"((d)[0]), "+f"((d)[1]), "+f"((d)[2]), "+f"((d)[3]) \
        : "r"((a)[0]), "r"((a)[1]), "r"((a)[2]), "r"((a)[3]), "r"(b0v), "r"(b1v))

// dynamic smem layout for k_aggr (single stage)
#define SA_HI   0
#define SA_LO   16384
#define SB_HI   32768
#define SB_LO   49152
#define SM_PART 65536
#define SM_RINV 66560
#define SM_TOT  67072

// ---------------------------------------------------------------------------
// K0: zero stats accumulators
// ---------------------------------------------------------------------------
__global__ void k_zero() {
    int t = threadIdx.x;
    if (t < 768) g_stats[t] = 0.f;
}

// ---------------------------------------------------------------------------
// Kp: transpose P -> Pt_hi / Pt_lo (bf16 split), [b][d][j]
// ---------------------------------------------------------------------------
__global__ __launch_bounds__(256) void k_prep(const float* __restrict__ P) {
    __shared__ float s[32][33];
    int b = blockIdx.z, j0 = blockIdx.x * 32, d0 = blockIdx.y * 32;
    int t = threadIdx.x;
    {
        int jr = t >> 3, dq = (t & 7) * 4;
        float4 v = *(const float4*)(P + ((long)b * NN + j0 + jr) * DD + d0 + dq);
        s[jr][dq + 0] = v.x; s[jr][dq + 1] = v.y; s[jr][dq + 2] = v.z; s[jr][dq + 3] = v.w;
    }
    __syncthreads();
    int d = t >> 3, jq = (t & 7) * 4;
    float x0 = s[jq + 0][d], x1 = s[jq + 1][d], x2 = s[jq + 2][d], x3 = s[jq + 3][d];
    uint32_t h01 = prmt_hi(__float_as_uint(x0), __float_as_uint(x1));
    uint32_t h23 = prmt_hi(__float_as_uint(x2), __float_as_uint(x3));
    uint32_t l01 = cvt_bf16x2(x0 - trunc_bf(x0), x1 - trunc_bf(x1));
    uint32_t l23 = cvt_bf16x2(x2 - trunc_bf(x2), x3 - trunc_bf(x3));
    long off = ((long)b * DD + d0 + d) * NN + j0 + jq;
    *(uint2*)(g_pt_hi + off) = make_uint2(h01, h23);
    *(uint2*)(g_pt_lo + off) = make_uint2(l01, l23);
}

// ---------------------------------------------------------------------------
// K1: bf16-split HMMA aggr.  CTA: batch b, 128 rows i0, one edge tensor.
//   acc[128,128] = masked-E(128xK) @ Pt(K x 128), K=512, chunks of 64.
//   3 mma passes per chunk: Ah*Bh + Ah*Bl + Al*Bh.  Epilogue: L1 row norm.
// Warps: 8 = (wr 0..3) x (wc 0..1); warp tile 32m x 64n.
// ---------------------------------------------------------------------------
extern __shared__ __align__(1024) char dsm[];

__global__ __launch_bounds__(256, 2) void k_aggr(const float* __restrict__ Ed,
                                                 const float* __restrict__ Ei) {
    const uint32_t sb = smem_u32(dsm);
    const int tid = threadIdx.x;
    const int lane = tid & 31, wid = tid >> 5;
    const int wr = wid >> 1, wc = wid & 1;
    const int b = blockIdx.y, i0 = blockIdx.x * 128, edge = blockIdx.z;
    const float* E = edge ? Ei : Ed;

    // producer mapping: row r, k-half
    const int r = tid >> 1;
    const int colbase = (tid & 1) * 32;
    const int irow = i0 + r;
    const float* Erow = E + ((long)b * NN + irow) * NN + colbase;
    const __nv_bfloat16* Bh = g_pt_hi + ((long)b * DD + r) * NN + colbase;
    const __nv_bfloat16* Bl = g_pt_lo + ((long)b * DD + r) * NN + colbase;
    float rs = 0.f;

    // ldmatrix per-lane address components
    const int a_rin = (lane & 7) + ((lane >> 3) & 1) * 8;   // row within m16
    const int a_kb  = ((lane >> 3) >> 1) * 16;              // k-half byte offset
    const int a_row = wr * 32 + a_rin;
    const uint32_t a_xm = (uint32_t)((a_row & 7) << 4);
    const uint32_t aA_base = sb + (uint32_t)(a_row * 128);

    const int b_nin = (lane & 7) + (lane >= 16 ? 8 : 0);
    const int b_kb  = ((lane >> 3) & 1) * 16;
    const uint32_t b_xm = (uint32_t)(((b_nin & 7)) << 4);
    const uint32_t bB_base = sb + (uint32_t)((wc * 64 + b_nin) * 128);

    float acc[2][8][4];
    #pragma unroll
    for (int mf = 0; mf < 2; mf++)
        #pragma unroll
        for (int nf = 0; nf < 8; nf++)
            #pragma unroll
            for (int q = 0; q < 4; q++) acc[mf][nf][q] = 0.f;

    for (int c = 0; c < 8; c++) {
        const int k0 = c * 64;

        // ---- producer: load + mask + split E rows, copy Pt ----
        float4 v[8];
        #pragma unroll
        for (int u = 0; u < 8; u++) v[u] = *(const float4*)(Erow + k0 + u * 4);
        #pragma unroll
        for (int u = 0; u < 8; u++) {
            int jb = k0 + colbase + u * 4;
            if (jb + 0 == irow) v[u].x = 0.f;
            if (jb + 1 == irow) v[u].y = 0.f;
            if (jb + 2 == irow) v[u].z = 0.f;
            if (jb + 3 == irow) v[u].w = 0.f;
            rs += v[u].x + v[u].y + v[u].z + v[u].w;
        }
        #pragma unroll
        for (int u2 = 0; u2 < 4; u2++) {
            float4 a = v[2 * u2], q = v[2 * u2 + 1];
            uint4 hv = make_uint4(
                prmt_hi(__float_as_uint(a.x), __float_as_uint(a.y)),
                prmt_hi(__float_as_uint(a.z), __float_as_uint(a.w)),
                prmt_hi(__float_as_uint(q.x), __float_as_uint(q.y)),
                prmt_hi(__float_as_uint(q.z), __float_as_uint(q.w)));
            uint4 lv = make_uint4(
                cvt_bf16x2(a.x - trunc_bf(a.x), a.y - trunc_bf(a.y)),
                cvt_bf16x2(a.z - trunc_bf(a.z), a.w - trunc_bf(a.w)),
                cvt_bf16x2(q.x - trunc_bf(q.x), q.y - trunc_bf(q.y)),
                cvt_bf16x2(q.z - trunc_bf(q.z), q.w - trunc_bf(q.w)));
            uint32_t off = r * 128 + colbase * 2 + u2 * 16;
            uint32_t sw = off ^ ((off >> 3) & 0x70);
            *(uint4*)(dsm + SA_HI + sw) = hv;
            *(uint4*)(dsm + SA_LO + sw) = lv;
        }
        #pragma unroll
        for (int u2 = 0; u2 < 4; u2++) {
            uint4 hv = *(const uint4*)(Bh + k0 + u2 * 8);
            uint4 lv = *(const uint4*)(Bl + k0 + u2 * 8);
            uint32_t off = r * 128 + colbase * 2 + u2 * 16;
            uint32_t sw = off ^ ((off >> 3) & 0x70);
            *(uint4*)(dsm + SB_HI + sw) = hv;
            *(uint4*)(dsm + SB_LO + sw) = lv;
        }
        __syncthreads();

        // ---- consumer: ldmatrix + mma (3 passes) ----
        #pragma unroll
        for (int ks = 0; ks < 4; ks++) {
            const uint32_t kA = ((uint32_t)(ks * 32 + a_kb)) ^ a_xm;
            uint32_t ah[2][4], al[2][4];
            LDMX4(ah[0], aA_base + SA_HI + kA);
            LDMX4(ah[1], aA_base + SA_HI + 2048 + kA);
            LDMX4(al[0], aA_base + SA_LO + kA);
            LDMX4(al[1], aA_base + SA_LO + 2048 + kA);

            const uint32_t kB = ((uint32_t)(ks * 32 + b_kb)) ^ b_xm;
            #pragma unroll
            for (int nh = 0; nh < 2; nh++) {
                uint32_t bh[2][4], bl[2][4];
                LDMX4(bh[0], bB_base + SB_HI + (uint32_t)(nh * 32 * 128) + kB);
                LDMX4(bh[1], bB_base + SB_HI + (uint32_t)((nh * 32 + 16) * 128) + kB);
                LDMX4(bl[0], bB_base + SB_LO + (uint32_t)(nh * 32 * 128) + kB);
                LDMX4(bl[1], bB_base + SB_LO + (uint32_t)((nh * 32 + 16) * 128) + kB);
                #pragma unroll
                for (int nf4 = 0; nf4 < 4; nf4++) {
                    const int qq = nf4 >> 1, hh = (nf4 & 1) * 2;
                    const int nf = nh * 4 + nf4;
                    #pragma unroll
                    for (int mf = 0; mf < 2; mf++) {
                        MMA_BF16(acc[mf][nf], ah[mf], bh[qq][hh], bh[qq][hh + 1]);
                        MMA_BF16(acc[mf][nf], ah[mf], bl[qq][hh], bl[qq][hh + 1]);
                        MMA_BF16(acc[mf][nf], al[mf], bh[qq][hh], bh[qq][hh + 1]);
                    }
                }
            }
        }
        __syncthreads();
    }

    // ---- row sums -> inverse ----
    ((float*)(dsm + SM_PART))[tid] = rs;
    __syncthreads();
    if (tid < 128) {
        float s = ((float*)(dsm + SM_PART))[2 * tid] + ((float*)(dsm + SM_PART))[2 * tid + 1];
        ((float*)(dsm + SM_RINV))[tid] = 1.f / fmaxf(s, 1e-12f);
    }
    __syncthreads();

    // ---- epilogue: scale + store ----
    const float* rinv = (const float*)(dsm + SM_RINV);
    #pragma unroll
    for (int mf = 0; mf < 2; mf++) {
        const int lr0 = wr * 32 + mf * 16 + (lane >> 2);
        const float inv0 = rinv[lr0], inv1 = rinv[lr0 + 8];
        float* d0 = g_xcat + ((long)(b * NN + i0 + lr0)) * C1 + edge * 128 + wc * 64 + 2 * (lane & 3);
        float* d1 = d0 + 8L * C1;
        #pragma unroll
        for (int nf = 0; nf < 8; nf++) {
            *(float2*)(d0 + nf * 8) = make_float2(acc[mf][nf][0] * inv0, acc[mf][nf][1] * inv0);
            *(float2*)(d1 + nf * 8) = make_float2(acc[mf][nf][2] * inv1, acc[mf][nf][3] * inv1);
        }
    }
}

// ---------------------------------------------------------------------------
// K2: h1[m,o] = sum_c xcat[m,c] * W1[o,c]  + per-channel stats
// ---------------------------------------------------------------------------
__global__ __launch_bounds__(256) void k_gemm1(const float* __restrict__ W1) {
    __shared__ __align__(16) float sA[32][64];
    __shared__ __align__(16) float sW[32][256];
    __shared__ float ssum[256];
    __shared__ float ssq[256];

    const long m0 = (long)blockIdx.x * 64;
    const int tid = threadIdx.x;
    const int c = tid & 31, r = tid >> 5;

    u64 acc[4][8];
    #pragma unroll
    for (int x = 0; x < 4; x++)
        #pragma unroll
        for (int y = 0; y < 8; y++) acc[x][y] = 0ULL;

    ssum[tid] = 0.f; ssq[tid] = 0.f;

    for (int k0 = 0; k0 < C1; k0 += 32) {
        #pragma unroll
        for (int t = 0; t < 2; t++) {
            int idx = tid + t * 256;
            int row = idx >> 3;
            int col = (idx & 7) << 2;
            float4 v = *(const float4*)&g_xcat[(m0 + row) * C1 + k0 + col];
            sA[col + 0][row] = v.x; sA[col + 1][row] = v.y;
            sA[col + 2][row] = v.z; sA[col + 3][row] = v.w;
        }
        #pragma unroll
        for (int t = 0; t < 8; t++) {
            int idx = tid + t * 256;
            int o = idx >> 3;
            int col = (idx & 7) << 2;
            float4 v = *(const float4*)&W1[o * C1 + k0 + col];
            sW[col + 0][o] = v.x; sW[col + 1][o] = v.y;
            sW[col + 2][o] = v.z; sW[col + 3][o] = v.w;
        }
        __syncthreads();
        #pragma unroll
        for (int jj = 0; jj < 32; jj++) {
            const float* ap = &sA[jj][r * 8];
            ulonglong2 av0 = *(const ulonglong2*)ap;
            ulonglong2 av1 = *(const ulonglong2*)(ap + 4);
            u64 a2[4] = {av0.x, av0.y, av1.x, av1.y};
            float bf[8];
            *(float4*)bf       = *(const float4*)&sW[jj][c * 8];
            *(float4*)(bf + 4) = *(const float4*)&sW[jj][c * 8 + 4];
            u64 bd[8];
            #pragma unroll
            for (int y = 0; y < 8; y++) bd[y] = pack2(bf[y], bf[y]);
            #pragma unroll
            for (int x = 0; x < 4; x++)
                #pragma unroll
                for (int y = 0; y < 8; y++)
                    acc[x][y] = fma2(a2[x], bd[y], acc[x][y]);
        }
        __syncthreads();
    }

    float psum[8], psq[8];
    #pragma unroll
    for (int y = 0; y < 8; y++) { psum[y] = 0.f; psq[y] = 0.f; }

    #pragma unroll
    for (int x = 0; x < 4; x++) {
        float lo[8], hi[8];
        #pragma unroll
        for (int y = 0; y < 8; y++) {
            unpack2(acc[x][y], lo[y], hi[y]);
            psum[y] += lo[y] + hi[y];
            psq[y]  += lo[y] * lo[y] + hi[y] * hi[y];
        }
        #pragma unroll
        for (int s = 0; s < 2; s++) {
            int lrow = r * 8 + 2 * x + s;
            float* sel = s ? hi : lo;
            float4* dst = (float4*)&g_h1[(m0 + lrow) * C1 + c * 8];
            dst[0] = make_float4(sel[0], sel[1], sel[2], sel[3]);
            dst[1] = make_float4(sel[4], sel[5], sel[6], sel[7]);
        }
    }
    #pragma unroll
    for (int y = 0; y < 8; y++) {
        atomicAdd(&ssum[c * 8 + y], psum[y]);
        atomicAdd(&ssq[c * 8 + y], psq[y]);
    }
    __syncthreads();
    atomicAdd(&g_stats[tid], ssum[tid]);
    atomicAdd(&g_stats[256 + tid], ssq[tid]);
}

// ---------------------------------------------------------------------------
// K3/K5: stats -> (scale, shift)
// ---------------------------------------------------------------------------
__global__ void k_bnaff(const float* __restrict__ g, const float* __restrict__ b,
                        int C, int statoff, int affoff) {
    int o = threadIdx.x;
    if (o < C) {
        const float inv_cnt = 1.f / 131072.f;
        float mean = g_stats[statoff + o] * inv_cnt;
        float var  = g_stats[statoff + C + o] * inv_cnt - mean * mean;
        float sc = g[o] * rsqrtf(var + 1e-5f);
        g_aff[affoff + o]     = sc;
        g_aff[affoff + C + o] = b[o] - mean * sc;
    }
}

// ---------------------------------------------------------------------------
// K4: h2[m,o] = sum_c lrelu(scale1[c]*h1[m,c]+shift1[c]) * W2[o,c] + stats
// ---------------------------------------------------------------------------
__global__ __launch_bounds__(256) void k_gemm2(const float* __restrict__ W2) {
    __shared__ __align__(16) float sA[32][64];
    __shared__ __align__(16) float sW[32][128];
    __shared__ float saff[2][256];
    __shared__ float ssum[128];
    __shared__ float ssq[128];

    const long m0 = (long)blockIdx.x * 64;
    const int tid = threadIdx.x;
    const int c = tid & 31, r = tid >> 5;

    saff[0][tid] = g_aff[tid];
    saff[1][tid] = g_aff[256 + tid];
    if (tid < 128) { ssum[tid] = 0.f; ssq[tid] = 0.f; }

    u64 acc[4][4];
    #pragma unroll
    for (int x = 0; x < 4; x++)
        #pragma unroll
        for (int y = 0; y < 4; y++) acc[x][y] = 0ULL;

    __syncthreads();

    for (int k0 = 0; k0 < C1; k0 += 32) {
        #pragma unroll
        for (int t = 0; t < 2; t++) {
            int idx = tid + t * 256;
            int row = idx >> 3;
            int col = (idx & 7) << 2;
            float4 v = *(const float4*)&g_h1[(m0 + row) * C1 + k0 + col];
            int ch = k0 + col;
            v.x = lrelu(saff[0][ch + 0] * v.x + saff[1][ch + 0]);
            v.y = lrelu(saff[0][ch + 1] * v.y + saff[1][ch + 1]);
            v.z = lrelu(saff[0][ch + 2] * v.z + saff[1][ch + 2]);
            v.w = lrelu(saff[0][ch + 3] * v.w + saff[1][ch + 3]);
            sA[col + 0][row] = v.x; sA[col + 1][row] = v.y;
            sA[col + 2][row] = v.z; sA[col + 3][row] = v.w;
        }
        #pragma unroll
        for (int t = 0; t < 4; t++) {
            int idx = tid + t * 256;
            int o = idx >> 3;
            int col = (idx & 7) << 2;
            float4 v = *(const float4*)&W2[o * C1 + k0 + col];
            sW[col + 0][o] = v.x; sW[col + 1][o] = v.y;
            sW[col + 2][o] = v.z; sW[col + 3][o] = v.w;
        }
        __syncthreads();
        #pragma unroll
        for (int jj = 0; jj < 32; jj++) {
            const float* ap = &sA[jj][r * 8];
            ulonglong2 av0 = *(const ulonglong2*)ap;
            ulonglong2 av1 = *(const ulonglong2*)(ap + 4);
            u64 a2[4] = {av0.x, av0.y, av1.x, av1.y};
            float bf[4];
            *(float4*)bf = *(const float4*)&sW[jj][c * 4];
            u64 bd[4];
            #pragma unroll
            for (int y = 0; y < 4; y++) bd[y] = pack2(bf[y], bf[y]);
            #pragma unroll
            for (int x = 0; x < 4; x++)
                #pragma unroll
                for (int y = 0; y < 4; y++)
                    acc[x][y] = fma2(a2[x], bd[y], acc[x][y]);
        }
        __syncthreads();
    }

    float psum[4], psq[4];
    #pragma unroll
    for (int y = 0; y < 4; y++) { psum[y] = 0.f; psq[y] = 0.f; }

    #pragma unroll
    for (int x = 0; x < 4; x++) {
        float lo[4], hi[4];
        #pragma unroll
        for (int y = 0; y < 4; y++) {
            unpack2(acc[x][y], lo[y], hi[y]);
            psum[y] += lo[y] + hi[y];
            psq[y]  += lo[y] * lo[y] + hi[y] * hi[y];
        }
        #pragma unroll
        for (int s = 0; s < 2; s++) {
            int lrow = r * 8 + 2 * x + s;
            float* sel = s ? hi : lo;
            *(float4*)&g_h2[(m0 + lrow) * C2 + c * 4] =
                make_float4(sel[0], sel[1], sel[2], sel[3]);
        }
    }
    #pragma unroll
    for (int y = 0; y < 4; y++) {
        atomicAdd(&ssum[c * 4 + y], psum[y]);
        atomicAdd(&ssq[c * 4 + y], psq[y]);
    }
    __syncthreads();
    if (tid < 128) {
        atomicAdd(&g_stats[512 + tid], ssum[tid]);
        atomicAdd(&g_stats[640 + tid], ssq[tid]);
    }
}

// ---------------------------------------------------------------------------
// K6: out = lrelu(scale2*h2 + shift2)
// ---------------------------------------------------------------------------
__global__ __launch_bounds__(256) void k_final(float* __restrict__ out) {
    long idx = ((long)blockIdx.x * blockDim.x + threadIdx.x);
    long e = idx * 4;
    int ch = (int)(e & 127);
    float4 v = *(const float4*)&g_h2[e];
    v.x = lrelu(g_aff[512 + ch + 0] * v.x + g_aff[640 + ch + 0]);
    v.y = lrelu(g_aff[512 + ch + 1] * v.y + g_aff[640 + ch + 1]);
    v.z = lrelu(g_aff[512 + ch + 2] * v.z + g_aff[640 + ch + 2]);
    v.w = lrelu(g_aff[512 + ch + 3] * v.w + g_aff[640 + ch + 3]);
    *(float4*)&out[e] = v;
}

// ---------------------------------------------------------------------------
extern "C" void kernel_launch(void* const* d_in, const int* in_sizes, int n_in,
                              void* d_out, int out_size) {
    const float* Ed = (const float*)d_in[0];
    const float* Ei = (const float*)d_in[1];
    const float* P  = (const float*)d_in[2];
    const float* W1 = (const float*)d_in[3];
    const float* g1 = (const float*)d_in[4];
    const float* b1 = (const float*)d_in[5];
    const float* W2 = (const float*)d_in[6];
    const float* g2 = (const float*)d_in[7];
    const float* b2 = (const float*)d_in[8];
    float* out = (float*)d_out;

    cudaFuncSetAttribute((const void*)k_aggr,
                         cudaFuncAttributeMaxDynamicSharedMemorySize, SM_TOT);

    k_zero<<<1, 768>>>();
    k_prep<<<dim3(16, 4, 256), 256>>>(P);
    k_aggr<<<dim3(4, 256, 2), 256, SM_TOT>>>(Ed, Ei);
    k_gemm1<<<(int)(BN_ / 64), 256>>>(W1);
    k_bnaff<<<1, 256>>>(g1, b1, 256, 0, 0);
    k_gemm2<<<(int)(BN_ / 64), 256>>>(W2);
    k_bnaff<<<1, 128>>>(g2, b2, 128, 512, 512);
    k_final<<<(int)(BN_ * C2 / 4 / 256), 256>>>(out);
}